// round 11
// baseline (speedup 1.0000x reference)
#include <cuda_runtime.h>

#define P_RAYS 262144
#define FULLM 0xFFFFFFFFu
#define RGRID 1024

__device__ float g_part0[RGRID];
__device__ float g_part1[RGRID];
__device__ int   g_cntp[RGRID];
__device__ int   g_done = 0;
__device__ float g_mean0;
__device__ float g_mean1;

// Fused reduce: per-block partials + deterministic last-block final reduce.
__global__ void __launch_bounds__(256) k_reduce(const float* __restrict__ rd,
                                                const float* __restrict__ cam) {
    __shared__ float4 st4[192];                 // 256 rays = 192 float4
    __shared__ float  w0s[8], w1s[8];
    __shared__ int    wcs[8];
    __shared__ float  f0[256], f1[256];
    __shared__ int    fc[256];
    __shared__ int    s_last;

    const int tid = threadIdx.x;
    const float4* rd4 = reinterpret_cast<const float4*>(rd);
    if (tid < 192) st4[tid] = rd4[blockIdx.x * 192 + tid];
    __syncthreads();

    const float cx = cam[0], cy = cam[1], cz = cam[2];
    const float cc = cx * cx + cy * cy + cz * cz;
    const float* sf = reinterpret_cast<const float*>(st4);

    float a0 = 0.f, a1 = 0.f; int cnt = 0;
    {
        const float dx = sf[3 * tid + 0];
        const float dy = sf[3 * tid + 1];
        const float dz = sf[3 * tid + 2];
        float dot = dx * cx + dy * cy + dz * cz;
        float under = dot * dot - (cc - 1.0f);
        if (under > 0.0f) {
            float sq = sqrtf(under);
            a0 = -sq - dot; a1 = sq - dot; cnt = 1;
        }
    }
    #pragma unroll
    for (int off = 16; off > 0; off >>= 1) {
        a0  += __shfl_down_sync(FULLM, a0, off);
        a1  += __shfl_down_sync(FULLM, a1, off);
        cnt += __shfl_down_sync(FULLM, cnt, off);
    }
    const int wid = tid >> 5, lane = tid & 31;
    if (lane == 0) { w0s[wid] = a0; w1s[wid] = a1; wcs[wid] = cnt; }
    __syncthreads();
    if (tid == 0) {
        float b0 = 0.f, b1 = 0.f; int bc = 0;
        #pragma unroll
        for (int i = 0; i < 8; i++) { b0 += w0s[i]; b1 += w1s[i]; bc += wcs[i]; }
        g_part0[blockIdx.x] = b0;
        g_part1[blockIdx.x] = b1;
        g_cntp[blockIdx.x]  = bc;
        __threadfence();
        int v = atomicAdd(&g_done, 1);
        s_last = (v == RGRID - 1) ? 1 : 0;
    }
    __syncthreads();
    if (s_last) {
        // final reduce, fixed order -> deterministic
        volatile float* p0 = g_part0;
        volatile float* p1 = g_part1;
        volatile int*   pc = g_cntp;
        float b0 = (p0[tid] + p0[tid + 256]) + (p0[tid + 512] + p0[tid + 768]);
        float b1 = (p1[tid] + p1[tid + 256]) + (p1[tid + 512] + p1[tid + 768]);
        int   bc = (pc[tid] + pc[tid + 256]) + (pc[tid + 512] + pc[tid + 768]);
        f0[tid] = b0; f1[tid] = b1; fc[tid] = bc;
        __syncthreads();
        for (int s = 128; s > 0; s >>= 1) {
            if (tid < s) { f0[tid] += f0[tid + s]; f1[tid] += f1[tid + s]; fc[tid] += fc[tid + s]; }
            __syncthreads();
        }
        if (tid == 0) {
            float n = (float)(fc[0] > 1 ? fc[0] : 1);
            g_mean0 = f0[0] / n;
            g_mean1 = f1[0] / n;
            g_done = 0;                       // reset for next graph replay
        }
    }
}

// Main kernel: TWO RAYS PER WARP (16 lanes/ray, 4 steps/lane).
// Scans via width-16 shuffles; sampling + output transposes via warp-private smem.
__global__ void __launch_bounds__(256) k_main(const float* __restrict__ rd,
                                              const float* __restrict__ cam,
                                              const float* __restrict__ trand,
                                              float* __restrict__ out) {
    __shared__ float s_steps[8][128];   // [warp][half*64 + j]  (reused for z later)
    __shared__ float s_cdf[8][128];
    __shared__ float s_w[8][128];

    const int tid  = threadIdx.x;
    const int wid  = tid >> 5;
    const int lane = tid & 31;
    const int h    = lane & 15;
    const int half = lane >> 4;
    const int r    = ((blockIdx.x << 3) + wid) * 2 + half;

    const float cx = cam[0], cy = cam[1], cz = cam[2];
    const float cc = cx * cx + cy * cy + cz * cz;

    const float dx = __ldg(rd + 3 * r + 0);
    const float dy = __ldg(rd + 3 * r + 1);
    const float dz = __ldg(rd + 3 * r + 2);
    const float dot = dx * cx + dy * cy + dz * cz;
    const float under = dot * dot - (cc - 1.0f);

    float si0, si1;
    if (under > 0.0f) {
        float sq = sqrtf(under);
        si0 = -sq - dot;
        si1 =  sq - dot;
    } else {
        si0 = g_mean0;
        si1 = g_mean1;
    }
    const float min_d = fmaxf(si0, 0.0f);
    const float max_d = fmaxf(si1, 0.0f);
    const float range = max_d - min_d;
    const float sd = range * (1.0f / 64.0f);

    const float K  = -28.977304500f;   // -e^3 * log2(e)
    const float Kh =  14.488652250f;

    const float4 t4 = reinterpret_cast<const float4*>(trand)[(size_t)r * 16 + h];
    const float tr[4] = {t4.x, t4.y, t4.z, t4.w};

    float step[4], sig[4], bb[4];
    #pragma unroll
    for (int i = 0; i < 4; i++) {
        int j = 4 * h + i;
        step[i] = fmaf((float)j * (1.0f / 63.0f), range, min_d) + (tr[i] - 0.5f) * sd;
        float q = fmaxf(fmaf(step[i], step[i] + 2.0f * dot, cc), 1e-12f);
        float sq = q * rsqrtf(q);
        bb[i] = exp2f(fmaf(sq, K, Kh));
        sig[i] = __fdividef(1.0f, 1.0f + bb[i]);
    }

    float signext = __shfl_down_sync(FULLM, sig[0], 1, 16);

    float alpha[4];
    #pragma unroll
    for (int i = 0; i < 4; i++) {
        float snext = (i < 3) ? sig[i + 1] : signext;
        float ib = 1.0f + bb[i];
        float invse = ib * (1.0f - 1e-8f * ib);     // ~ 1/(sig+1e-8)
        float a = (sig[i] - snext + 1e-8f) * invse;
        alpha[i] = fminf(fmaxf(a, 0.0f), 1.0f);
    }
    if (h == 15) alpha[3] = 0.0f;

    // transmittance: product scan over 64 slots
    float g0 = 1.0f - alpha[0] + 1e-7f;
    float g1 = 1.0f - alpha[1] + 1e-7f;
    float g2 = 1.0f - alpha[2] + 1e-7f;
    float g3 = 1.0f - alpha[3] + 1e-7f;
    float m1 = g0, m2 = m1 * g1, m3 = m2 * g2, m4 = m3 * g3;
    float incl = m4;
    #pragma unroll
    for (int off = 1; off < 16; off <<= 1) {
        float v = __shfl_up_sync(FULLM, incl, off, 16);
        if (h >= off) incl *= v;
    }
    float excl = __shfl_up_sync(FULLM, incl, 1, 16);
    if (h == 0) excl = 1.0f;

    float w0 = alpha[0] * excl;
    float w1 = alpha[1] * (excl * m1);
    float w2 = alpha[2] * (excl * m2);
    float w3 = alpha[3] * (excl * m3);

    // unnormalized CDF: sum scan of (w + 1e-8)
    float p1 = w0 + 1e-8f;
    float p2 = p1 + (w1 + 1e-8f);
    float p3 = p2 + (w2 + 1e-8f);
    float p4 = p3 + (w3 + 1e-8f);
    float sinc = p4;
    #pragma unroll
    for (int off = 1; off < 16; off <<= 1) {
        float v = __shfl_up_sync(FULLM, sinc, off, 16);
        if (h >= off) sinc += v;
    }
    float sexcl = __shfl_up_sync(FULLM, sinc, 1, 16);
    if (h == 0) sexcl = 0.0f;
    float c0 = sexcl + p1;
    float c1 = sexcl + p2;
    float c2 = sexcl + p3;
    float c3 = sexcl + p4;

    const float wsum = __shfl_sync(FULLM, c2, 15, 16);   // C[62]
    const float invW = __fdividef(1.0f, wsum);

    // register pivots for top 2 search levels (values = C[15], C[31], C[47])
    const float c15 = __shfl_sync(FULLM, c3, 3, 16);
    const float c31 = __shfl_sync(FULLM, c3, 7, 16);
    const float c47 = __shfl_sync(FULLM, c3, 11, 16);

    // stage steps, cdf, w into warp-private smem
    float* ss = &s_steps[wid][half * 64];
    float* sc = &s_cdf[wid][half * 64];
    float* sw = &s_w[wid][half * 64];
    *reinterpret_cast<float4*>(ss + 4 * h) = make_float4(step[0], step[1], step[2], step[3]);
    *reinterpret_cast<float4*>(sc + 4 * h) = make_float4(c0, c1, c2, c3);
    *reinterpret_cast<float4*>(sw + 4 * h) = make_float4(w0, w1, w2, w3);
    __syncwarp();

    // weights out: strided coalesced scalar stores
    {
        float* wout = out + (size_t)P_RAYS * 128 + (size_t)r * 63;
        #pragma unroll
        for (int i = 0; i < 4; i++) {
            int j = h + 16 * i;
            if (j < 63) wout[j] = sw[j];
        }
    }

    // importance sampling: lane handles samples 2h, 2h+1
    float z2[2];
    #pragma unroll
    for (int u = 0; u < 2; u++) {
        int k = 2 * h + u;
        float target = (float)(2 * k + 1) * (1.0f / 64.0f) * wsum;

        bool top = (c31 <= target);
        int p = top ? 32 : 0;
        float piv = top ? c47 : c15;
        if (piv <= target) p += 16;
        #pragma unroll
        for (int s = 8; s > 0; s >>= 1) {
            int np = p + s;                    // np-1 <= 62 always
            if (sc[np - 1] <= target) p = np;
        }
        // p <= 62 guaranteed (target < C[62])
        float cdf_b = (p == 0) ? 0.0f : sc[p - 1];
        float cdf_a = sc[p];
        float bins_b = ss[p];
        float bins_a = ss[p + 1];
        float dN = cdf_a - cdf_b;
        float tt = (target - cdf_b) * ((dN < 1e-8f * wsum) ? invW : __fdividef(1.0f, dN));
        z2[u] = fmaf(tt, bins_a - bins_b, bins_b);
    }

    // z out: float2 per lane (coalesced)
    *reinterpret_cast<float2*>(out + (size_t)P_RAYS * 96 + (size_t)r * 32 + 2 * h) =
        make_float2(z2[0], z2[1]);

    // stage z into (reused) steps smem, then assemble float4 windows of new_samples
    __syncwarp();
    *reinterpret_cast<float2*>(ss + 2 * h) = make_float2(z2[0], z2[1]);
    __syncwarp();

    {
        float* nsrow = out + (size_t)r * 96;
        #pragma unroll
        for (int pass = 0; pass < 2; pass++) {
            int m = (pass == 0) ? h : (h + 16);
            if (pass == 1 && h >= 8) break;
            int qq = m / 3;
            int t = m - 3 * qq;
            int k0 = 4 * qq + t;
            float za = ss[k0];
            float zb = ss[k0 + 1];
            float4 v;
            if (t == 0) {
                v = make_float4(fmaf(za, dx, cx), fmaf(za, dy, cy),
                                fmaf(za, dz, cz), fmaf(zb, dx, cx));
            } else if (t == 1) {
                v = make_float4(fmaf(za, dy, cy), fmaf(za, dz, cz),
                                fmaf(zb, dx, cx), fmaf(zb, dy, cy));
            } else {
                v = make_float4(fmaf(za, dz, cz), fmaf(zb, dx, cx),
                                fmaf(zb, dy, cy), fmaf(zb, dz, cz));
            }
            reinterpret_cast<float4*>(nsrow)[m] = v;
        }
    }
}

extern "C" void kernel_launch(void* const* d_in, const int* in_sizes, int n_in,
                              void* d_out, int out_size) {
    const float* rd  = (const float*)d_in[0];
    const float* cam = (const float*)d_in[1];
    const float* tr  = (const float*)d_in[2];
    float* out = (float*)d_out;

    k_reduce<<<RGRID, 256>>>(rd, cam);
    k_main<<<P_RAYS / 16, 256>>>(rd, cam, tr, out);
}

// round 14
// speedup vs baseline: 1.1539x; 1.1539x over previous
#include <cuda_runtime.h>

#define P_RAYS 262144
#define FULLM 0xFFFFFFFFu
#define RGRID 1024

__device__ float g_part0[RGRID];
__device__ float g_part1[RGRID];
__device__ int   g_cntp[RGRID];
__device__ int   g_done = 0;
__device__ float g_mean0;
__device__ float g_mean1;

// Fused reduce: per-block partials + deterministic last-block final reduce.
__global__ void __launch_bounds__(256) k_reduce(const float* __restrict__ rd,
                                                const float* __restrict__ cam) {
    __shared__ float4 st4[192];                 // 256 rays = 192 float4
    __shared__ float  w0s[8], w1s[8];
    __shared__ int    wcs[8];
    __shared__ float  f0[256], f1[256];
    __shared__ int    fc[256];
    __shared__ int    s_last;

    const int tid = threadIdx.x;
    const float4* rd4 = reinterpret_cast<const float4*>(rd);
    if (tid < 192) st4[tid] = rd4[blockIdx.x * 192 + tid];
    __syncthreads();

    const float cx = cam[0], cy = cam[1], cz = cam[2];
    const float cc = cx * cx + cy * cy + cz * cz;
    const float* sf = reinterpret_cast<const float*>(st4);

    float a0 = 0.f, a1 = 0.f; int cnt = 0;
    {
        const float dx = sf[3 * tid + 0];
        const float dy = sf[3 * tid + 1];
        const float dz = sf[3 * tid + 2];
        float dot = dx * cx + dy * cy + dz * cz;
        float under = dot * dot - (cc - 1.0f);
        if (under > 0.0f) {
            float sq = sqrtf(under);
            a0 = -sq - dot; a1 = sq - dot; cnt = 1;
        }
    }
    #pragma unroll
    for (int off = 16; off > 0; off >>= 1) {
        a0  += __shfl_down_sync(FULLM, a0, off);
        a1  += __shfl_down_sync(FULLM, a1, off);
        cnt += __shfl_down_sync(FULLM, cnt, off);
    }
    const int wid = tid >> 5, lane = tid & 31;
    if (lane == 0) { w0s[wid] = a0; w1s[wid] = a1; wcs[wid] = cnt; }
    __syncthreads();
    if (tid == 0) {
        float b0 = 0.f, b1 = 0.f; int bc = 0;
        #pragma unroll
        for (int i = 0; i < 8; i++) { b0 += w0s[i]; b1 += w1s[i]; bc += wcs[i]; }
        g_part0[blockIdx.x] = b0;
        g_part1[blockIdx.x] = b1;
        g_cntp[blockIdx.x]  = bc;
        __threadfence();
        int v = atomicAdd(&g_done, 1);
        s_last = (v == RGRID - 1) ? 1 : 0;
    }
    __syncthreads();
    if (s_last) {
        volatile float* p0 = g_part0;
        volatile float* p1 = g_part1;
        volatile int*   pc = g_cntp;
        float b0 = (p0[tid] + p0[tid + 256]) + (p0[tid + 512] + p0[tid + 768]);
        float b1 = (p1[tid] + p1[tid + 256]) + (p1[tid + 512] + p1[tid + 768]);
        int   bc = (pc[tid] + pc[tid + 256]) + (pc[tid + 512] + pc[tid + 768]);
        f0[tid] = b0; f1[tid] = b1; fc[tid] = bc;
        __syncthreads();
        for (int s = 128; s > 0; s >>= 1) {
            if (tid < s) { f0[tid] += f0[tid + s]; f1[tid] += f1[tid + s]; fc[tid] += fc[tid + s]; }
            __syncthreads();
        }
        if (tid == 0) {
            float n = (float)(fc[0] > 1 ? fc[0] : 1);
            g_mean0 = f0[0] / n;
            g_mean1 = f1[0] / n;
            g_done = 0;                       // reset for next graph replay
        }
    }
}

// Main kernel: TWO RAYS PER WARP (16 lanes/ray, 4 steps/lane).
// R9 structure (direct register stores), trimmed-LDS binary search.
__global__ void __launch_bounds__(256) k_main(const float* __restrict__ rd,
                                              const float* __restrict__ cam,
                                              const float* __restrict__ trand,
                                              float* __restrict__ out) {
    __shared__ float s_steps[8][128];   // [warp][half*64 + j]
    __shared__ float s_cdf[8][128];

    const int tid  = threadIdx.x;
    const int wid  = tid >> 5;
    const int lane = tid & 31;
    const int h    = lane & 15;
    const int half = lane >> 4;
    const int r    = ((blockIdx.x << 3) + wid) * 2 + half;

    const float cx = cam[0], cy = cam[1], cz = cam[2];
    const float cc = cx * cx + cy * cy + cz * cz;

    const float dx = __ldg(rd + 3 * r + 0);
    const float dy = __ldg(rd + 3 * r + 1);
    const float dz = __ldg(rd + 3 * r + 2);
    const float dot = dx * cx + dy * cy + dz * cz;
    const float under = dot * dot - (cc - 1.0f);

    float si0, si1;
    if (under > 0.0f) {
        float sq = sqrtf(under);
        si0 = -sq - dot;
        si1 =  sq - dot;
    } else {
        si0 = g_mean0;
        si1 = g_mean1;
    }
    const float min_d = fmaxf(si0, 0.0f);
    const float max_d = fmaxf(si1, 0.0f);
    const float range = max_d - min_d;
    const float sd = range * (1.0f / 64.0f);

    const float K  = -28.977304500f;   // -e^3 * log2(e)
    const float Kh =  14.488652250f;

    const float4 t4 = reinterpret_cast<const float4*>(trand)[(size_t)r * 16 + h];
    const float tr[4] = {t4.x, t4.y, t4.z, t4.w};

    float step[4], sig[4], bb[4];
    #pragma unroll
    for (int i = 0; i < 4; i++) {
        int j = 4 * h + i;
        step[i] = fmaf((float)j * (1.0f / 63.0f), range, min_d) + (tr[i] - 0.5f) * sd;
        float q = fmaxf(fmaf(step[i], step[i] + 2.0f * dot, cc), 1e-12f);
        float sq = q * rsqrtf(q);
        bb[i] = exp2f(fmaf(sq, K, Kh));
        sig[i] = __fdividef(1.0f, 1.0f + bb[i]);
    }

    float signext = __shfl_down_sync(FULLM, sig[0], 1, 16);

    float alpha[4];
    #pragma unroll
    for (int i = 0; i < 4; i++) {
        float snext = (i < 3) ? sig[i + 1] : signext;
        float ib = 1.0f + bb[i];
        float invse = ib * (1.0f - 1e-8f * ib);     // ~ 1/(sig+1e-8)
        float a = (sig[i] - snext + 1e-8f) * invse;
        alpha[i] = fminf(fmaxf(a, 0.0f), 1.0f);
    }
    if (h == 15) alpha[3] = 0.0f;

    // transmittance: product scan over 64 slots
    float g0 = 1.0f - alpha[0] + 1e-7f;
    float g1 = 1.0f - alpha[1] + 1e-7f;
    float g2 = 1.0f - alpha[2] + 1e-7f;
    float g3 = 1.0f - alpha[3] + 1e-7f;
    float m1 = g0, m2 = m1 * g1, m3 = m2 * g2, m4 = m3 * g3;
    float incl = m4;
    #pragma unroll
    for (int off = 1; off < 16; off <<= 1) {
        float v = __shfl_up_sync(FULLM, incl, off, 16);
        if (h >= off) incl *= v;
    }
    float excl = __shfl_up_sync(FULLM, incl, 1, 16);
    if (h == 0) excl = 1.0f;

    float w0 = alpha[0] * excl;
    float w1 = alpha[1] * (excl * m1);
    float w2 = alpha[2] * (excl * m2);
    float w3 = alpha[3] * (excl * m3);

    // unnormalized CDF: sum scan of (w + 1e-8)
    float p1 = w0 + 1e-8f;
    float p2 = p1 + (w1 + 1e-8f);
    float p3 = p2 + (w2 + 1e-8f);
    float p4 = p3 + (w3 + 1e-8f);
    float sinc = p4;
    #pragma unroll
    for (int off = 1; off < 16; off <<= 1) {
        float v = __shfl_up_sync(FULLM, sinc, off, 16);
        if (h >= off) sinc += v;
    }
    float sexcl = __shfl_up_sync(FULLM, sinc, 1, 16);
    if (h == 0) sexcl = 0.0f;
    float c0 = sexcl + p1;
    float c1 = sexcl + p2;
    float c2 = sexcl + p3;
    float c3 = sexcl + p4;

    const float wsum = __shfl_sync(FULLM, c2, 15, 16);   // C[62]
    const float invW = __fdividef(1.0f, wsum);

    // register pivots: C[15], C[31], C[47]
    const float c15 = __shfl_sync(FULLM, c3, 3, 16);
    const float c31 = __shfl_sync(FULLM, c3, 7, 16);
    const float c47 = __shfl_sync(FULLM, c3, 11, 16);

    // stage steps + cdf into warp-private smem (needed for sampling)
    float* ss = &s_steps[wid][half * 64];
    float* sc = &s_cdf[wid][half * 64];
    *reinterpret_cast<float4*>(ss + 4 * h) = make_float4(step[0], step[1], step[2], step[3]);
    *reinterpret_cast<float4*>(sc + 4 * h) = make_float4(c0, c1, c2, c3);
    __syncwarp();

    // weights out: direct from registers (j = 4h..4h+3, j<63)
    {
        float* wout = out + (size_t)P_RAYS * 128 + (size_t)r * 63 + 4 * h;
        wout[0] = w0; wout[1] = w1; wout[2] = w2;
        if (h < 15) wout[3] = w3;
    }

    // importance sampling: lane handles samples 2h, 2h+1
    float z2[2];
    #pragma unroll
    for (int u = 0; u < 2; u++) {
        int k = 2 * h + u;
        float target = (float)(2 * k + 1) * (1.0f / 64.0f) * wsum;

        // top 2 levels from register pivots; track cdf_b through accepted probes
        int p = 0;
        float cb = 0.0f;
        if (c31 <= target) { p = 32; cb = c31; }
        float piv = (p == 32) ? c47 : c15;
        if (piv <= target) { p += 16; cb = piv; }
        #pragma unroll
        for (int s = 8; s > 0; s >>= 1) {
            float v = sc[p + s - 1];           // index <= 62 always
            if (v <= target) { p += s; cb = v; }
        }
        // p <= 62 guaranteed (target < C[62]); cb = C[p-1] (0 if p==0)
        float cdf_a = sc[p];
        float bins_b = ss[p];
        float bins_a = ss[p + 1];
        float dN = cdf_a - cb;
        float tt = (target - cb) * ((dN < 1e-8f * wsum) ? invW : __fdividef(1.0f, dN));
        z2[u] = fmaf(tt, bins_a - bins_b, bins_b);
    }

    // z out: float2 per lane (coalesced)
    *reinterpret_cast<float2*>(out + (size_t)P_RAYS * 96 + (size_t)r * 32 + 2 * h) =
        make_float2(z2[0], z2[1]);

    // new_samples out: 6 floats per lane as 3x float2 (8B aligned), direct
    {
        float* nsout = out + (size_t)r * 96 + 6 * h;
        *reinterpret_cast<float2*>(nsout + 0) =
            make_float2(fmaf(z2[0], dx, cx), fmaf(z2[0], dy, cy));
        *reinterpret_cast<float2*>(nsout + 2) =
            make_float2(fmaf(z2[0], dz, cz), fmaf(z2[1], dx, cx));
        *reinterpret_cast<float2*>(nsout + 4) =
            make_float2(fmaf(z2[1], dy, cy), fmaf(z2[1], dz, cz));
    }
}

extern "C" void kernel_launch(void* const* d_in, const int* in_sizes, int n_in,
                              void* d_out, int out_size) {
    const float* rd  = (const float*)d_in[0];
    const float* cam = (const float*)d_in[1];
    const float* tr  = (const float*)d_in[2];
    float* out = (float*)d_out;

    k_reduce<<<RGRID, 256>>>(rd, cam);
    k_main<<<P_RAYS / 16, 256>>>(rd, cam, tr, out);
}